// round 6
// baseline (speedup 1.0000x reference)
#include <cuda_runtime.h>
#include <cuda_fp16.h>
#include <cstdint>

#define BATCH 256
#define TVIS 32
#define BT 8192
#define CN 4880
#define CNP 5120           // padded to 20*256
#define MN 1000
#define MNP 1024           // padded to 4*256
#define HD 128
#define R3H 384
#define OUTN 4880

// ------------- static device scratch -------------
__device__ __half g_Hch[(size_t)CNP * HD];   // fp16 tanh(c_emb@W_c), pad rows zero
__device__ __half g_Hmh[(size_t)MNP * HD];   // fp16 tanh(m_emb@W_m), pad rows zero
__device__ float g_sumc[BT * HD];
__device__ float g_cntc[BT];
__device__ float g_summ[BT * HD];
__device__ float g_cntm[BT];
__device__ float g_repre[(size_t)BT * R3H];
__device__ float g_scores[BT];
__device__ float g_ctx[BATCH * R3H];

// ---------------- helpers ----------------
__device__ __forceinline__ void cp_async16(unsigned saddr, const void* gptr) {
    asm volatile("cp.async.cg.shared.global [%0], [%1], 16;" :: "r"(saddr), "l"(gptr) : "memory");
}
__device__ __forceinline__ void cp_commit() {
    asm volatile("cp.async.commit_group;" ::: "memory");
}
__device__ __forceinline__ void cp_wait1() {
    asm volatile("cp.async.wait_group 1;" ::: "memory");
}
__device__ __forceinline__ unsigned long long pack2(float lo, float hi) {
    unsigned long long r;
    asm("mov.b64 %0, {%1, %2};" : "=l"(r) : "f"(lo), "f"(hi));
    return r;
}
__device__ __forceinline__ void fma2(unsigned long long& d, unsigned long long a, unsigned long long b) {
    asm("fma.rn.f32x2 %0, %1, %2, %0;" : "+l"(d) : "l"(a), "l"(b));
}
__device__ __forceinline__ float2 unpack2(unsigned long long v) {
    float lo, hi;
    asm("mov.b64 {%0, %1}, %2;" : "=f"(lo), "=f"(hi) : "l"(v));
    return make_float2(lo, hi);
}

// =============== K1: H = tanh(emb @ W) -> fp16 (pad rows -> tanh(0)=0) ===============
__global__ void k1_tanh_gemm(const float* __restrict__ emb, const float* __restrict__ W,
                             int which, int rows, int rowOffset)
{
    extern __shared__ float sm[];
    float* Wt  = sm;               // [128][132]
    float* esh = sm + 128 * 132;   // [8][128]
    __half* out = which ? g_Hmh : g_Hch;
    const int tid = threadIdx.x;   // 128

    for (int k = 0; k < 128; k++)
        Wt[tid * 132 + k] = W[k * 128 + tid];
    __syncthreads();

    const int rowBase = rowOffset + blockIdx.x * 32;
    const float4* wr = reinterpret_cast<const float4*>(Wt + tid * 132);
    for (int rg = 0; rg < 4; rg++) {
        const int r0 = rowBase + rg * 8;
        for (int i = tid; i < 8 * 128; i += 128) {
            int r = i >> 7;
            int row = r0 + r;
            esh[i] = (row < rows) ? emb[row * 128 + (i & 127)] : 0.f;
        }
        __syncthreads();
        float acc[8] = {0.f,0.f,0.f,0.f,0.f,0.f,0.f,0.f};
        #pragma unroll 4
        for (int k4 = 0; k4 < 32; k4++) {
            float4 w = wr[k4];
            #pragma unroll
            for (int r = 0; r < 8; r++) {
                float4 e = reinterpret_cast<const float4*>(esh + r * 128)[k4];
                acc[r] = fmaf(w.x, e.x, acc[r]);
                acc[r] = fmaf(w.y, e.y, acc[r]);
                acc[r] = fmaf(w.z, e.z, acc[r]);
                acc[r] = fmaf(w.w, e.w, acc[r]);
            }
        }
        #pragma unroll
        for (int r = 0; r < 8; r++)
            out[(size_t)(r0 + r) * 128 + tid] = __float2half(tanhf(acc[r]));
        __syncthreads();
    }
}

// =============== K2 fused: sparse code + med aggregation ===============
// 147 blocks x 448 threads (14 warps), 4 visits/warp (56/block, covers 8232>=8192).
// Chunks of 256 H-rows (64 KB fp16) double-buffered via cp.async.
// Half-warp split: lanes 0-15 walk chunk codes [0,128), lanes 16-31 walk [128,256).
// Each lane owns h[(lane&15)*8 .. +8): one LDS.128 + 4 HFMA2 per gather.
// fp16 accumulate within a chunk, flushed to fp32 each chunk.
#define K2T 448
#define K2W 14
#define VPW 4
#define VPB (K2W * VPW)       // 56
#define KC 256
#define NCHC 20
#define NCHM 4
#define NCHT (NCHC + NCHM)
#define BUFH (KC * HD)        // 32768 halves = 64 KB
#define CHUNK_U4 4096         // uint4 per chunk

// per-visit 8-bit nonzero mask for this lane's 8 slice values
__device__ __forceinline__ void k2_load_masks(int* msk, const float* __restrict__ code_x,
                                              const float* __restrict__ med,
                                              int vbase, int c, int lane)
{
    const bool isMed = (c >= NCHC);
    const int  kb    = (isMed ? (c - NCHC) : c) * KC + lane * 8;
    const int  limit = isMed ? MN : CN;
    #pragma unroll
    for (int i = 0; i < VPW; i++) {
        int v = vbase + i;
        int m = 0;
        if (kb + 7 < limit && v < BT) {
            const float* row = isMed ? (med + (size_t)v * MN) : (code_x + (size_t)v * CN);
            const float4* p = reinterpret_cast<const float4*>(row + kb);
            float4 a = p[0], b = p[1];
            m  = (a.x != 0.f) ? 1 : 0;
            m |= (a.y != 0.f) ? 2 : 0;
            m |= (a.z != 0.f) ? 4 : 0;
            m |= (a.w != 0.f) ? 8 : 0;
            m |= (b.x != 0.f) ? 16 : 0;
            m |= (b.y != 0.f) ? 32 : 0;
            m |= (b.z != 0.f) ? 64 : 0;
            m |= (b.w != 0.f) ? 128 : 0;
        }
        msk[i] = m;
    }
}

__global__ void __launch_bounds__(K2T, 1) k2_fused(const float* __restrict__ code_x,
                                                   const float* __restrict__ med)
{
    extern __shared__ __align__(16) __half sh[];   // 2 x 32768 halves = 128 KB
    const int tid = threadIdx.x, warp = tid >> 5, lane = tid & 31;
    const int vbase = blockIdx.x * VPB + warp * VPW;
    const unsigned sbase = (unsigned)__cvta_generic_to_shared(sh);
    const uint4* HcV = reinterpret_cast<const uint4*>(g_Hch);
    const uint4* HmV = reinterpret_cast<const uint4*>(g_Hmh);
    const unsigned halfSel = (lane < 16) ? 0x0000FFFFu : 0xFFFF0000u;
    const int p8 = (lane & 15) * 8;                // this lane's h base
    const __half2 ONE2 = __float2half2_rn(1.f);
    const __half2 ZERO2 = __float2half2_rn(0.f);

    float2 facc[4][VPW];
    int    cnt[VPW];
    #pragma unroll
    for (int q = 0; q < 4; q++)
        #pragma unroll
        for (int i = 0; i < VPW; i++) facc[q][i] = make_float2(0.f, 0.f);
    #pragma unroll
    for (int i = 0; i < VPW; i++) cnt[i] = 0;

    // prefetch chunk 0
    #pragma unroll
    for (int s = 0; s < 10; s++) {
        int i = tid + s * K2T;
        if (i < CHUNK_U4) cp_async16(sbase + (unsigned)i * 16u, HcV + i);
    }
    cp_commit();

    int nxt[VPW];
    k2_load_masks(nxt, code_x, med, vbase, 0, lane);

    for (int c = 0; c < NCHT; c++) {
        if (c + 1 < NCHT) {
            const uint4* src = (c + 1 < NCHC) ? (HcV + (size_t)(c + 1) * CHUNK_U4)
                                              : (HmV + (size_t)(c + 1 - NCHC) * CHUNK_U4);
            const unsigned sb = sbase + (unsigned)(((c + 1) & 1) * BUFH) * 2u;
            #pragma unroll
            for (int s = 0; s < 10; s++) {
                int i = tid + s * K2T;
                if (i < CHUNK_U4) cp_async16(sb + (unsigned)i * 16u, src + i);
            }
        }
        cp_commit();
        cp_wait1();
        __syncthreads();

        int cur[VPW];
        #pragma unroll
        for (int i = 0; i < VPW; i++) cur[i] = nxt[i];
        if (c + 1 < NCHT) k2_load_masks(nxt, code_x, med, vbase, c + 1, lane);

        const __half* buf = sh + (c & 1) * BUFH;

        __half2 hacc[4][VPW];
        #pragma unroll
        for (int q = 0; q < 4; q++)
            #pragma unroll
            for (int i = 0; i < VPW; i++) hacc[q][i] = ZERO2;

        #pragma unroll
        for (int i = 0; i < VPW; i++) {
            int mymask = cur[i];
            #pragma unroll
            for (int j = 0; j < 8; j++) {
                unsigned m = __ballot_sync(0xffffffffu, (mymask >> j) & 1);
                cnt[i] += __popc(m);
                unsigned ml = m & halfSel;         // this half-warp's stream
                while (__any_sync(0xffffffffu, ml != 0u)) {
                    bool have = (ml != 0u);
                    int s = have ? (__ffs(ml) - 1) : (lane & 16);  // benign addr when idle
                    ml &= ml - 1u;                 // 0 stays 0
                    const uint4 hv = *reinterpret_cast<const uint4*>(
                        buf + (unsigned)(s * 8 + j) * HD + p8);
                    const __half2* h2 = reinterpret_cast<const __half2*>(&hv);
                    __half2 f = have ? ONE2 : ZERO2;
                    hacc[0][i] = __hfma2(h2[0], f, hacc[0][i]);
                    hacc[1][i] = __hfma2(h2[1], f, hacc[1][i]);
                    hacc[2][i] = __hfma2(h2[2], f, hacc[2][i]);
                    hacc[3][i] = __hfma2(h2[3], f, hacc[3][i]);
                }
            }
        }

        // flush fp16 chunk sums into fp32
        #pragma unroll
        for (int i = 0; i < VPW; i++)
            #pragma unroll
            for (int q = 0; q < 4; q++) {
                float2 t = __half22float2(hacc[q][i]);
                facc[q][i].x += t.x;
                facc[q][i].y += t.y;
            }

        if (c == NCHC - 1) {
            // reduce halves and store code outputs, then reset
            #pragma unroll
            for (int i = 0; i < VPW; i++) {
                #pragma unroll
                for (int q = 0; q < 4; q++) {
                    facc[q][i].x += __shfl_xor_sync(0xffffffffu, facc[q][i].x, 16);
                    facc[q][i].y += __shfl_xor_sync(0xffffffffu, facc[q][i].y, 16);
                }
                int v = vbase + i;
                if (v < BT) {
                    float* dst = g_sumc + (size_t)v * HD + p8;
                    if (lane < 16)
                        *reinterpret_cast<float4*>(dst) =
                            make_float4(facc[0][i].x, facc[0][i].y, facc[1][i].x, facc[1][i].y);
                    else
                        *reinterpret_cast<float4*>(dst + 4) =
                            make_float4(facc[2][i].x, facc[2][i].y, facc[3][i].x, facc[3][i].y);
                    if (lane == 0) g_cntc[v] = (float)cnt[i];
                }
                cnt[i] = 0;
                #pragma unroll
                for (int q = 0; q < 4; q++) facc[q][i] = make_float2(0.f, 0.f);
            }
        }
        __syncthreads();
    }

    // store med outputs
    #pragma unroll
    for (int i = 0; i < VPW; i++) {
        #pragma unroll
        for (int q = 0; q < 4; q++) {
            facc[q][i].x += __shfl_xor_sync(0xffffffffu, facc[q][i].x, 16);
            facc[q][i].y += __shfl_xor_sync(0xffffffffu, facc[q][i].y, 16);
        }
        int v = vbase + i;
        if (v < BT) {
            float* dst = g_summ + (size_t)v * HD + p8;
            if (lane < 16)
                *reinterpret_cast<float4*>(dst) =
                    make_float4(facc[0][i].x, facc[0][i].y, facc[1][i].x, facc[1][i].y);
            else
                *reinterpret_cast<float4*>(dst + 4) =
                    make_float4(facc[2][i].x, facc[2][i].y, facc[3][i].x, facc[3][i].y);
            if (lane == 0) g_cntm[v] = (float)cnt[i];
        }
    }
}

// =============== K3: repre + attention scores (Wa in smem) ===============
__global__ void __launch_bounds__(512) k3_repre_scores(const float* __restrict__ Wa,
                                                       const float* __restrict__ ba,
                                                       const float* __restrict__ va)
{
    extern __shared__ float dsm[];
    float* WaS = dsm;                            // 384*32
    float* rsh = dsm + R3H * 32;                 // 16*384

    const int tid = threadIdx.x, warp = tid >> 5, lane = tid & 31;
    const int v = blockIdx.x * 16 + warp;        // grid 512 -> 8192

    for (int i = tid; i < R3H * 32; i += 512) WaS[i] = Wa[i];

    float invc = 1.f / fmaxf(g_cntc[v], 1.f);
    float invm = 1.f / fmaxf(g_cntm[v], 1.f);
    float4 sc = reinterpret_cast<const float4*>(g_sumc + (size_t)v * HD)[lane];
    float4 sm_ = reinterpret_cast<const float4*>(g_summ + (size_t)v * HD)[lane];
    float4 hc = make_float4(sc.x*invc, sc.y*invc, sc.z*invc, sc.w*invc);
    float4 hm = make_float4(sm_.x*invm, sm_.y*invm, sm_.z*invm, sm_.w*invm);
    float4 hp = make_float4(hc.x*hm.x, hc.y*hm.y, hc.z*hm.z, hc.w*hm.w);

    float* r = rsh + warp * R3H;
    reinterpret_cast<float4*>(r)[lane] = hc;
    reinterpret_cast<float4*>(r + HD)[lane] = hm;
    reinterpret_cast<float4*>(r + 2*HD)[lane] = hp;
    float* gr = g_repre + (size_t)v * R3H;
    reinterpret_cast<float4*>(gr)[lane] = hc;
    reinterpret_cast<float4*>(gr + HD)[lane] = hm;
    reinterpret_cast<float4*>(gr + 2*HD)[lane] = hp;
    __syncthreads();

    float s0 = 0.f, s1 = 0.f;
    #pragma unroll 4
    for (int d = 0; d < R3H; d += 2) {
        s0 = fmaf(r[d],     WaS[d * 32 + lane],       s0);
        s1 = fmaf(r[d + 1], WaS[(d + 1) * 32 + lane], s1);
    }
    float t = tanhf(s0 + s1 + ba[lane]) * va[lane];
    #pragma unroll
    for (int o = 16; o > 0; o >>= 1) t += __shfl_xor_sync(0xffffffffu, t, o);
    if (lane == 0) g_scores[v] = t;
}

// =============== K4: masked softmax + context ===============
__global__ void k4_attn_ctx(const int* __restrict__ lens)
{
    __shared__ float at[TVIS];
    const int b = blockIdx.x, tid = threadIdx.x;
    if (tid < 32) {
        int len = lens[b];
        float s = g_scores[b * TVIS + tid];
        bool valid = tid < len;
        float sv = valid ? s : -1e30f;
        float mx = sv;
        #pragma unroll
        for (int o = 16; o > 0; o >>= 1) mx = fmaxf(mx, __shfl_xor_sync(0xffffffffu, mx, o));
        float e = valid ? __expf(sv - mx) : 0.f;
        float sum = e;
        #pragma unroll
        for (int o = 16; o > 0; o >>= 1) sum += __shfl_xor_sync(0xffffffffu, sum, o);
        at[tid] = e / sum;
    }
    __syncthreads();
    for (int d = tid; d < R3H; d += blockDim.x) {
        float acc = 0.f;
        const float* rp = g_repre + (size_t)b * TVIS * R3H + d;
        #pragma unroll 8
        for (int t = 0; t < TVIS; t++) acc = fmaf(at[t], rp[t * R3H], acc);
        g_ctx[b * R3H + d] = acc;
    }
}

// =============== K5: sigmoid(ctx @ W_cls + b) — 80 blocks, LDS.128, f32x2 FMA ===============
__global__ void __launch_bounds__(512) k5_classifier(const float* __restrict__ Wc,
                                                     const float* __restrict__ bc,
                                                     float* __restrict__ out)
{
    extern __shared__ float sctx[];   // [384][36] transposed ctx (16B-aligned rows)
    const int tid = threadIdx.x;      // 512
    const int row0 = blockIdx.y * 32;

    for (int i = tid; i < 32 * R3H; i += 512) {
        int r = i / R3H, k = i - r * R3H;
        sctx[k * 36 + r] = g_ctx[(row0 + r) * R3H + k];
    }
    __syncthreads();

    const int n = blockIdx.x * 512 + tid;   // grid.x=10 -> 5120 >= 4880
    const bool v = n < OUTN;

    unsigned long long A[16];
    #pragma unroll
    for (int i = 0; i < 16; i++) A[i] = 0ull;

    float wq[4];
    #pragma unroll
    for (int i = 0; i < 4; i++) wq[i] = v ? Wc[(size_t)i * OUTN + n] : 0.f;

    #pragma unroll 4
    for (int k = 0; k < R3H; k++) {
        float w = wq[k & 3];
        if (k + 4 < R3H) wq[k & 3] = v ? Wc[(size_t)(k + 4) * OUTN + n] : 0.f;
        unsigned long long p = pack2(w, w);
        const float4* cp4 = reinterpret_cast<const float4*>(sctx + k * 36);
        #pragma unroll
        for (int rp = 0; rp < 8; rp++) {
            float4 cv = cp4[rp];                    // broadcast LDS.128
            fma2(A[2 * rp],     pack2(cv.x, cv.y), p);
            fma2(A[2 * rp + 1], pack2(cv.z, cv.w), p);
        }
    }

    if (v) {
        float b0 = bc[n];
        #pragma unroll
        for (int rp = 0; rp < 16; rp++) {
            float2 r2 = unpack2(A[rp]);
            int ra = row0 + 2 * rp;
            out[(size_t)ra * OUTN + n]       = 1.f / (1.f + __expf(-(r2.x + b0)));
            out[(size_t)(ra + 1) * OUTN + n] = 1.f / (1.f + __expf(-(r2.y + b0)));
        }
    }
}

// ============================== launch ==============================
extern "C" void kernel_launch(void* const* d_in, const int* in_sizes, int n_in,
                              void* d_out, int out_size)
{
    const float* code_x = (const float*)d_in[0];
    // d_in[1] divided, d_in[2] neighbors: dead inputs
    const int*   lens   = (const int*)d_in[3];
    const float* med    = (const float*)d_in[4];
    const float* c_emb  = (const float*)d_in[5];
    const float* m_emb  = (const float*)d_in[6];
    const float* W_c    = (const float*)d_in[7];
    const float* W_m    = (const float*)d_in[8];
    const float* Wa     = (const float*)d_in[9];
    const float* ba     = (const float*)d_in[10];
    const float* va     = (const float*)d_in[11];
    const float* W_cls  = (const float*)d_in[12];
    const float* b_cls  = (const float*)d_in[13];
    float* out = (float*)d_out;

    cudaFuncSetAttribute(k1_tanh_gemm,    cudaFuncAttributeMaxDynamicSharedMemorySize, 71680);
    cudaFuncSetAttribute(k2_fused,        cudaFuncAttributeMaxDynamicSharedMemorySize, 131072);
    cudaFuncSetAttribute(k3_repre_scores, cudaFuncAttributeMaxDynamicSharedMemorySize, 73728);
    cudaFuncSetAttribute(k5_classifier,   cudaFuncAttributeMaxDynamicSharedMemorySize, 55296);

    // k1 split in two so k2_fused sits at launch index 3 (ncu capture slot)
    k1_tanh_gemm<<<80, 128, 71680>>>(c_emb, W_c, 0, CN, 0);      // rows 0..2559
    k1_tanh_gemm<<<80, 128, 71680>>>(c_emb, W_c, 0, CN, 2560);   // rows 2560..5119
    k1_tanh_gemm<<<32, 128, 71680>>>(m_emb, W_m, 1, MN, 0);      // rows 0..1023
    k2_fused<<<147, K2T, 131072>>>(code_x, med);
    k3_repre_scores<<<512, 512, 73728>>>(Wa, ba, va);
    k4_attn_ctx<<<256, 128>>>(lens);
    k5_classifier<<<dim3(10, 8), 512, 55296>>>(W_cls, b_cls, out);
}

// round 7
// speedup vs baseline: 1.1900x; 1.1900x over previous
#include <cuda_runtime.h>
#include <cuda_fp16.h>
#include <cstdint>

#define BATCH 256
#define TVIS 32
#define BT 8192
#define CN 4880
#define CNP 5120           // padded to 20*256
#define MN 1000
#define MNP 1024
#define HD 128
#define R3H 384
#define OUTN 4880

// ------------- static device scratch -------------
__device__ __half g_Hch[(size_t)CNP * HD];   // fp16 tanh(c_emb@W_c), pad rows zero
__device__ __half g_Hmh[(size_t)MNP * HD];   // fp16 tanh(m_emb@W_m), pad rows zero
__device__ float g_sumc[BT * HD];
__device__ float g_cntc[BT];
__device__ float g_summ[BT * HD];
__device__ float g_cntm[BT];
__device__ float g_scores[BT];
__device__ float g_ctx[BATCH * R3H];

// ---------------- helpers ----------------
__device__ __forceinline__ void cp_async16(unsigned saddr, const void* gptr) {
    asm volatile("cp.async.cg.shared.global [%0], [%1], 16;" :: "r"(saddr), "l"(gptr) : "memory");
}
__device__ __forceinline__ void cp_commit() {
    asm volatile("cp.async.commit_group;" ::: "memory");
}
__device__ __forceinline__ void cp_wait1() {
    asm volatile("cp.async.wait_group 1;" ::: "memory");
}
__device__ __forceinline__ unsigned long long pack2(float lo, float hi) {
    unsigned long long r;
    asm("mov.b64 %0, {%1, %2};" : "=l"(r) : "f"(lo), "f"(hi));
    return r;
}
__device__ __forceinline__ void fma2(unsigned long long& d, unsigned long long a, unsigned long long b) {
    asm("fma.rn.f32x2 %0, %1, %2, %0;" : "+l"(d) : "l"(a), "l"(b));
}
__device__ __forceinline__ float2 unpack2(unsigned long long v) {
    float lo, hi;
    asm("mov.b64 {%0, %1}, %2;" : "=f"(lo), "=f"(hi) : "l"(v));
    return make_float2(lo, hi);
}

// =============== K1: H = tanh(emb @ W) -> fp16; W cached fp16 in smem ===============
// smem: Wth[128][138] halves (conflict-free pitch) + esh[8][128] floats = ~39 KB
__global__ void k1_tanh_gemm(const float* __restrict__ emb, const float* __restrict__ W,
                             int which, int rows)
{
    extern __shared__ float smf[];
    __half* Wth = reinterpret_cast<__half*>(smf);          // 128*138 halves = 35328 B
    float* esh  = smf + 35328 / 4;                         // [8][128] floats
    __half* out = which ? g_Hmh : g_Hch;
    const int tid = threadIdx.x;   // 128

    for (int k = 0; k < 128; k++)
        Wth[tid * 138 + k] = __float2half(W[k * 128 + tid]);
    __syncthreads();

    const int rowBase = blockIdx.x * 32;
    const __half2* wr = reinterpret_cast<const __half2*>(Wth + tid * 138);
    for (int rg = 0; rg < 4; rg++) {
        const int r0 = rowBase + rg * 8;
        for (int i = tid; i < 8 * 128; i += 128) {
            int r = i >> 7;
            int row = r0 + r;
            esh[i] = (row < rows) ? emb[row * 128 + (i & 127)] : 0.f;
        }
        __syncthreads();
        float acc[8] = {0.f,0.f,0.f,0.f,0.f,0.f,0.f,0.f};
        #pragma unroll 4
        for (int k4 = 0; k4 < 32; k4++) {
            float2 w01 = __half22float2(wr[2 * k4]);
            float2 w23 = __half22float2(wr[2 * k4 + 1]);
            #pragma unroll
            for (int r = 0; r < 8; r++) {
                float4 e = reinterpret_cast<const float4*>(esh + r * 128)[k4];
                acc[r] = fmaf(w01.x, e.x, acc[r]);
                acc[r] = fmaf(w01.y, e.y, acc[r]);
                acc[r] = fmaf(w23.x, e.z, acc[r]);
                acc[r] = fmaf(w23.y, e.w, acc[r]);
            }
        }
        #pragma unroll
        for (int r = 0; r < 8; r++)
            out[(size_t)(r0 + r) * 128 + tid] = __float2half(tanhf(acc[r]));
        __syncthreads();
    }
}

// =============== K2: sparse code aggregation (round-5 structure + HADD2) ===============
#define K2T 448
#define K2W 14
#define VPW 4
#define VPB (K2W * VPW)       // 56; grid 147 -> 8232 >= 8192
#define KC 256
#define NCH 20                // 5120/256
#define BUFH (KC * HD)        // 32768 halves = 64 KB
#define CHUNK_U4 4096

// 8-bit nonzero mask for this lane's 8 codes of chunk c, per visit
__device__ __forceinline__ void k2_load_masks(int* msk, const float* __restrict__ code_x,
                                              int vbase, int c, int lane)
{
    const int kb = c * KC + lane * 8;
    #pragma unroll
    for (int i = 0; i < VPW; i++) {
        int v = vbase + i;
        int m = 0;
        if (kb + 7 < CN && v < BT) {
            const float4* p = reinterpret_cast<const float4*>(code_x + (size_t)v * CN + kb);
            float4 a = p[0], b = p[1];
            m  = (a.x != 0.f) ? 1 : 0;
            m |= (a.y != 0.f) ? 2 : 0;
            m |= (a.z != 0.f) ? 4 : 0;
            m |= (a.w != 0.f) ? 8 : 0;
            m |= (b.x != 0.f) ? 16 : 0;
            m |= (b.y != 0.f) ? 32 : 0;
            m |= (b.z != 0.f) ? 64 : 0;
            m |= (b.w != 0.f) ? 128 : 0;
        }
        msk[i] = m;
    }
}

__global__ void __launch_bounds__(K2T, 1) k2_codes(const float* __restrict__ code_x)
{
    extern __shared__ __align__(16) __half sh[];   // 2 x 32768 halves = 128 KB
    const int tid = threadIdx.x, warp = tid >> 5, lane = tid & 31;
    const int vbase = blockIdx.x * VPB + warp * VPW;
    const unsigned sbase = (unsigned)__cvta_generic_to_shared(sh);
    const uint4* HcV = reinterpret_cast<const uint4*>(g_Hch);
    const int p4 = lane * 4;                       // this lane's 4 halves of an h row

    float4 facc[VPW];
    int    cnt[VPW];
    #pragma unroll
    for (int i = 0; i < VPW; i++) { facc[i] = make_float4(0,0,0,0); cnt[i] = 0; }

    // chunk 0 -> buffer 0
    #pragma unroll
    for (int s = 0; s < 10; s++) {
        int i = tid + s * K2T;
        if (i < CHUNK_U4) cp_async16(sbase + (unsigned)i * 16u, HcV + i);
    }
    cp_commit();

    int nxt[VPW];
    k2_load_masks(nxt, code_x, vbase, 0, lane);

    for (int c = 0; c < NCH; c++) {
        if (c + 1 < NCH) {
            const uint4* src = HcV + (size_t)(c + 1) * CHUNK_U4;
            const unsigned sb = sbase + (unsigned)(((c + 1) & 1) * BUFH) * 2u;
            #pragma unroll
            for (int s = 0; s < 10; s++) {
                int i = tid + s * K2T;
                if (i < CHUNK_U4) cp_async16(sb + (unsigned)i * 16u, src + i);
            }
        }
        cp_commit();
        cp_wait1();
        __syncthreads();

        int cur[VPW];
        #pragma unroll
        for (int i = 0; i < VPW; i++) cur[i] = nxt[i];
        if (c + 1 < NCH) k2_load_masks(nxt, code_x, vbase, c + 1, lane);

        const __half* buf = sh + (c & 1) * BUFH;

        #pragma unroll
        for (int i = 0; i < VPW; i++) {
            __half2 hacc0 = __float2half2_rn(0.f);
            __half2 hacc1 = __float2half2_rn(0.f);
            int mymask = cur[i];
            #pragma unroll
            for (int j = 0; j < 8; j++) {
                unsigned m = __ballot_sync(0xffffffffu, (mymask >> j) & 1);
                cnt[i] += __popc(m);
                while (m) {
                    int src = __ffs(m) - 1;
                    m &= m - 1;
                    const uint2 raw = *reinterpret_cast<const uint2*>(
                        buf + (unsigned)(src * 8 + j) * HD + p4);
                    hacc0 = __hadd2(hacc0, *reinterpret_cast<const __half2*>(&raw.x));
                    hacc1 = __hadd2(hacc1, *reinterpret_cast<const __half2*>(&raw.y));
                }
            }
            float2 f0 = __half22float2(hacc0);
            float2 f1 = __half22float2(hacc1);
            facc[i].x += f0.x; facc[i].y += f0.y;
            facc[i].z += f1.x; facc[i].w += f1.y;
        }
        __syncthreads();
    }

    #pragma unroll
    for (int i = 0; i < VPW; i++) {
        int v = vbase + i;
        if (v < BT) {
            reinterpret_cast<float4*>(g_sumc + (size_t)v * HD)[lane] = facc[i];
            if (lane == 0) g_cntc[v] = (float)cnt[i];
        }
    }
}

// =============== K2m: sparse med aggregation, fp16 gathers + HADD2 ===============
__global__ void k2_meds(const float* __restrict__ med)
{
    const int tid = threadIdx.x, warp = tid >> 5, lane = tid & 31;
    const int v = blockIdx.x * 8 + warp;       // grid 1024 -> 8192
    const float* row = med + (size_t)v * MN;

    float4 x[8];
    #pragma unroll
    for (int r = 0; r < 8; r++) {
        int kb = r * 128 + lane * 4;
        x[r] = make_float4(0,0,0,0);
        if (kb < MN)      // MN % 4 == 0
            x[r] = *reinterpret_cast<const float4*>(row + kb);
    }

    __half2 hacc0 = __float2half2_rn(0.f);
    __half2 hacc1 = __float2half2_rn(0.f);
    int cnt = 0;
    #pragma unroll
    for (int r = 0; r < 8; r++) {
        float xv[4] = {x[r].x, x[r].y, x[r].z, x[r].w};
        #pragma unroll
        for (int j = 0; j < 4; j++) {
            unsigned m = __ballot_sync(0xffffffffu, xv[j] != 0.f);
            cnt += __popc(m);
            while (m) {
                int s0 = __ffs(m) - 1; m &= m - 1;
                int s1 = -1;
                if (m) { s1 = __ffs(m) - 1; m &= m - 1; }
                int c0 = r * 128 + s0 * 4 + j;
                uint2 r0 = *reinterpret_cast<const uint2*>(g_Hmh + (size_t)c0 * HD + lane * 4);
                uint2 r1 = make_uint2(0u, 0u);
                if (s1 >= 0) {
                    int c1 = r * 128 + s1 * 4 + j;
                    r1 = *reinterpret_cast<const uint2*>(g_Hmh + (size_t)c1 * HD + lane * 4);
                }
                hacc0 = __hadd2(hacc0, __hadd2(*reinterpret_cast<const __half2*>(&r0.x),
                                               *reinterpret_cast<const __half2*>(&r1.x)));
                hacc1 = __hadd2(hacc1, __hadd2(*reinterpret_cast<const __half2*>(&r0.y),
                                               *reinterpret_cast<const __half2*>(&r1.y)));
            }
        }
    }
    float2 f0 = __half22float2(hacc0);
    float2 f1 = __half22float2(hacc1);
    reinterpret_cast<float4*>(g_summ + (size_t)v * HD)[lane] =
        make_float4(f0.x, f0.y, f1.x, f1.y);
    if (lane == 0) g_cntm[v] = (float)cnt;
}

// =============== K3+K4 fused: repre + scores + softmax + context, per batch ===============
// grid 256 (one block per batch), 512 threads (16 warps x 2 visits).
// smem: WaS[384*32] + rsh[32*384] + sc[32] + attn[32] = 98560 B
__global__ void __launch_bounds__(512) k3k4(const float* __restrict__ Wa,
                                            const float* __restrict__ ba,
                                            const float* __restrict__ va,
                                            const int* __restrict__ lens)
{
    extern __shared__ float dsm[];
    float* WaS  = dsm;                 // [384][32]
    float* rsh  = dsm + R3H * 32;      // [32][384]
    float* sc   = rsh + 32 * R3H;      // [32]
    float* attn = sc + 32;             // [32]

    const int b = blockIdx.x, tid = threadIdx.x;
    const int warp = tid >> 5, lane = tid & 31;

    for (int i = tid; i < R3H * 32; i += 512) WaS[i] = Wa[i];

    // build repre rows for this block's 32 visits (2 per warp)
    #pragma unroll
    for (int i = 0; i < 2; i++) {
        int t = warp * 2 + i;
        int v = b * TVIS + t;
        float invc = 1.f / fmaxf(g_cntc[v], 1.f);
        float invm = 1.f / fmaxf(g_cntm[v], 1.f);
        float4 scv = reinterpret_cast<const float4*>(g_sumc + (size_t)v * HD)[lane];
        float4 smv = reinterpret_cast<const float4*>(g_summ + (size_t)v * HD)[lane];
        float4 hc = make_float4(scv.x*invc, scv.y*invc, scv.z*invc, scv.w*invc);
        float4 hm = make_float4(smv.x*invm, smv.y*invm, smv.z*invm, smv.w*invm);
        float4 hp = make_float4(hc.x*hm.x, hc.y*hm.y, hc.z*hm.z, hc.w*hm.w);
        float* r = rsh + t * R3H;
        reinterpret_cast<float4*>(r)[lane] = hc;
        reinterpret_cast<float4*>(r + HD)[lane] = hm;
        reinterpret_cast<float4*>(r + 2*HD)[lane] = hp;
    }
    __syncthreads();

    // scores
    #pragma unroll
    for (int i = 0; i < 2; i++) {
        int t = warp * 2 + i;
        const float* r = rsh + t * R3H;
        float s0 = 0.f, s1 = 0.f;
        #pragma unroll 4
        for (int d = 0; d < R3H; d += 2) {
            s0 = fmaf(r[d],     WaS[d * 32 + lane],       s0);
            s1 = fmaf(r[d + 1], WaS[(d + 1) * 32 + lane], s1);
        }
        float tt = tanhf(s0 + s1 + ba[lane]) * va[lane];
        #pragma unroll
        for (int o = 16; o > 0; o >>= 1) tt += __shfl_xor_sync(0xffffffffu, tt, o);
        if (lane == 0) sc[t] = tt;
    }
    __syncthreads();

    // softmax over visits (warp 0, lane = visit)
    if (warp == 0) {
        int len = lens[b];
        bool valid = lane < len;
        float sv = valid ? sc[lane] : -1e30f;
        float mx = sv;
        #pragma unroll
        for (int o = 16; o > 0; o >>= 1) mx = fmaxf(mx, __shfl_xor_sync(0xffffffffu, mx, o));
        float e = valid ? __expf(sv - mx) : 0.f;
        float sum = e;
        #pragma unroll
        for (int o = 16; o > 0; o >>= 1) sum += __shfl_xor_sync(0xffffffffu, sum, o);
        attn[lane] = e / sum;
    }
    __syncthreads();

    // context
    if (tid < R3H) {
        float acc = 0.f;
        #pragma unroll 8
        for (int t = 0; t < TVIS; t++) acc = fmaf(attn[t], rsh[t * R3H + tid], acc);
        g_ctx[b * R3H + tid] = acc;
    }
}

// =============== K5: sigmoid(ctx @ W_cls + b) — LDS.128 broadcast, f32x2 FMA ===============
__global__ void __launch_bounds__(512) k5_classifier(const float* __restrict__ Wc,
                                                     const float* __restrict__ bc,
                                                     float* __restrict__ out)
{
    extern __shared__ float sctx[];   // [384][36] transposed ctx (16B-aligned rows)
    const int tid = threadIdx.x;      // 512
    const int row0 = blockIdx.y * 32;

    for (int i = tid; i < 32 * R3H; i += 512) {
        int r = i / R3H, k = i - r * R3H;
        sctx[k * 36 + r] = g_ctx[(row0 + r) * R3H + k];
    }
    __syncthreads();

    const int n = blockIdx.x * 512 + tid;   // grid.x=10 -> 5120 >= 4880
    const bool v = n < OUTN;

    unsigned long long A[16];
    #pragma unroll
    for (int i = 0; i < 16; i++) A[i] = 0ull;

    float wq[4];
    #pragma unroll
    for (int i = 0; i < 4; i++) wq[i] = v ? Wc[(size_t)i * OUTN + n] : 0.f;

    #pragma unroll 4
    for (int k = 0; k < R3H; k++) {
        float w = wq[k & 3];
        if (k + 4 < R3H) wq[k & 3] = v ? Wc[(size_t)(k + 4) * OUTN + n] : 0.f;
        unsigned long long p = pack2(w, w);
        const float4* cp4 = reinterpret_cast<const float4*>(sctx + k * 36);
        #pragma unroll
        for (int rp = 0; rp < 8; rp++) {
            float4 cv = cp4[rp];                    // broadcast LDS.128
            fma2(A[2 * rp],     pack2(cv.x, cv.y), p);
            fma2(A[2 * rp + 1], pack2(cv.z, cv.w), p);
        }
    }

    if (v) {
        float b0 = bc[n];
        #pragma unroll
        for (int rp = 0; rp < 16; rp++) {
            float2 r2 = unpack2(A[rp]);
            int ra = row0 + 2 * rp;
            out[(size_t)ra * OUTN + n]       = 1.f / (1.f + __expf(-(r2.x + b0)));
            out[(size_t)(ra + 1) * OUTN + n] = 1.f / (1.f + __expf(-(r2.y + b0)));
        }
    }
}

// ============================== launch ==============================
extern "C" void kernel_launch(void* const* d_in, const int* in_sizes, int n_in,
                              void* d_out, int out_size)
{
    const float* code_x = (const float*)d_in[0];
    // d_in[1] divided, d_in[2] neighbors: dead inputs
    const int*   lens   = (const int*)d_in[3];
    const float* med    = (const float*)d_in[4];
    const float* c_emb  = (const float*)d_in[5];
    const float* m_emb  = (const float*)d_in[6];
    const float* W_c    = (const float*)d_in[7];
    const float* W_m    = (const float*)d_in[8];
    const float* Wa     = (const float*)d_in[9];
    const float* ba     = (const float*)d_in[10];
    const float* va     = (const float*)d_in[11];
    const float* W_cls  = (const float*)d_in[12];
    const float* b_cls  = (const float*)d_in[13];
    float* out = (float*)d_out;

    const int SMEM_K1 = 35328 + 8 * 128 * 4;            // 39424
    cudaFuncSetAttribute(k1_tanh_gemm,  cudaFuncAttributeMaxDynamicSharedMemorySize, SMEM_K1);
    cudaFuncSetAttribute(k2_codes,      cudaFuncAttributeMaxDynamicSharedMemorySize, 131072);
    cudaFuncSetAttribute(k3k4,          cudaFuncAttributeMaxDynamicSharedMemorySize, 98560);
    cudaFuncSetAttribute(k5_classifier, cudaFuncAttributeMaxDynamicSharedMemorySize, 55296);

    k1_tanh_gemm<<<160, 128, SMEM_K1>>>(c_emb, W_c, 0, CN);   // g_Hch[5120x128], pad 0
    k1_tanh_gemm<<<32, 128, SMEM_K1>>>(m_emb, W_m, 1, MN);    // g_Hmh[1024x128], pad 0
    k2_meds<<<1024, 256>>>(med);
    k2_codes<<<147, K2T, 131072>>>(code_x);                   // index 3 = ncu capture slot
    k3k4<<<256, 512, 98560>>>(Wa, ba, va, lens);
    k5_classifier<<<dim3(10, 8), 512, 55296>>>(W_cls, b_cls, out);
}